// round 17
// baseline (speedup 1.0000x reference)
#include <cuda_runtime.h>
#include <cuda_fp16.h>
#include <cuda_bf16.h>
#include <cstdint>
#include <cstddef>

#define MAXN 100000
#define MAXE 1000000
#define NFEAT 64
#define NGRAPH 64

// ---------------- device scratch ----------------
__device__ __align__(128) float   g_A[(size_t)MAXN * NFEAT];   // node features h (fp32)
__device__ __align__(128) __half2 g_Bh[(size_t)MAXN * 32];     // (h@W)*dinv fp16; 128B/row
__device__ __align__(16) __nv_bfloat16 g_Wt_hi[3][NFEAT * NFEAT]; // W^T hi bf16 [layer][n*64+k]
__device__ __align__(16) __nv_bfloat16 g_Wt_lo[3][NFEAT * NFEAT]; // W^T lo bf16
__device__ int     g_cnt[MAXN];
__device__ int     g_excl[MAXN];
__device__ int     g_off[MAXN + 1];
__device__ int     g_cur[MAXN];
__device__ int     g_srcs[MAXE];
__device__ float   g_dinv[MAXN];
__device__ int     g_bsum[128];
__device__ int     g_bbase[128];
__device__ float   g_sums[NGRAPH * NFEAT];
__device__ int     g_gcnt[NGRAPH];

// ---------------- setup kernels ----------------
__global__ void k_zero(int N) {
    int i = blockIdx.x * blockDim.x + threadIdx.x;
    if (i < N) g_cnt[i] = 0;
    if (i < NGRAPH * NFEAT) g_sums[i] = 0.f;
    if (i < NGRAPH) g_gcnt[i] = 0;
}

__global__ void k_hist(const int* __restrict__ ei, int E) {
    int e = blockIdx.x * blockDim.x + threadIdx.x;
    if (e < E) atomicAdd(&g_cnt[ei[E + e]], 1);
}

// dinv + W^T split into hi/lo bf16 (Wt[n][k] = W[k][n]; lo = rn(w - float(hi)))
__global__ void k_dinv(int N, const float* __restrict__ W1,
                       const float* __restrict__ W2, const float* __restrict__ W3) {
    int i = blockIdx.x * blockDim.x + threadIdx.x;
    if (i < N) g_dinv[i] = rsqrtf((float)(g_cnt[i] + 1));  // +1 self loop
    if (i < 3 * NFEAT * NFEAT) {
        int l = i >> 12;
        int r = i & 4095;
        int n = r >> 6, k = r & 63;
        const float* Wp = (l == 0) ? W1 : ((l == 1) ? W2 : W3);
        float w = Wp[k * 64 + n];
        __nv_bfloat16 hi = __float2bfloat16(w);
        __nv_bfloat16 lo = __float2bfloat16(w - __bfloat162float(hi));
        g_Wt_hi[l][n * 64 + k] = hi;
        g_Wt_lo[l][n * 64 + k] = lo;
    }
}

__global__ void k_scan1(int N) {
    __shared__ int sm[1024];
    int t = threadIdx.x;
    int i = blockIdx.x * 1024 + t;
    int v = (i < N) ? g_cnt[i] : 0;
    sm[t] = v;
    __syncthreads();
    #pragma unroll
    for (int d = 1; d < 1024; d <<= 1) {
        int xv = (t >= d) ? sm[t - d] : 0;
        __syncthreads();
        sm[t] += xv;
        __syncthreads();
    }
    if (i < N) g_excl[i] = sm[t] - v;
    if (t == 1023) g_bsum[blockIdx.x] = sm[1023];
}

__global__ void k_scan2(int nb, int N) {
    __shared__ int sm[128];
    int t = threadIdx.x;
    int v = (t < nb) ? g_bsum[t] : 0;
    sm[t] = v;
    __syncthreads();
    #pragma unroll
    for (int d = 1; d < 128; d <<= 1) {
        int xv = (t >= d) ? sm[t - d] : 0;
        __syncthreads();
        sm[t] += xv;
        __syncthreads();
    }
    if (t < nb) g_bbase[t] = sm[t] - v;
    if (t == 127) g_off[N] = sm[127];
}

__global__ void k_scan3(int N) {
    int i = blockIdx.x * 1024 + threadIdx.x;
    if (i < N) {
        int o = g_excl[i] + g_bbase[blockIdx.x];
        g_off[i] = o;
        g_cur[i] = o;
    }
}

__global__ void k_place(const int* __restrict__ ei, int E) {
    int e = blockIdx.x * blockDim.x + threadIdx.x;
    if (e < E) {
        int s = ei[e];
        int d = ei[E + e];
        int p = atomicAdd(&g_cur[d], 1);
        g_srcs[p] = s;
    }
}

// ---------------- tensor-core GEMM via mma.sync, split-bf16 (3-MMA emulation) ----------------
// 128-row tile, 256 thr (8 warps). Dynamic smem 55.3KB:
//   xs_hi[128][72], xs_lo[128][72], wt_hi[64][72], wt_lo[64][72]
// Halves per-CTA W-staging traffic vs 64-row tile and doubles warps/CTA.
// D += Xhi*Whi + Xhi*Wlo + Xlo*Whi (lo*lo dropped, ~4e-6 rel).
#define XS_PAD 72
static constexpr int GEMM_SMEM = (128 * XS_PAD * 2 + 64 * XS_PAD * 2) * 2;  // 55296

__global__ void __launch_bounds__(256) k_gemm_mma(const float* __restrict__ Xext,
                                                  int N, int useExt, int layer) {
    extern __shared__ char smem_raw[];
    __nv_bfloat16 (*xs_hi)[XS_PAD] = (__nv_bfloat16(*)[XS_PAD])(smem_raw);
    __nv_bfloat16 (*xs_lo)[XS_PAD] = (__nv_bfloat16(*)[XS_PAD])(smem_raw + 18432);
    __nv_bfloat16 (*wt_hi)[XS_PAD] = (__nv_bfloat16(*)[XS_PAD])(smem_raw + 36864);
    __nv_bfloat16 (*wt_lo)[XS_PAD] = (__nv_bfloat16(*)[XS_PAD])(smem_raw + 46080);
    const float* __restrict__ X = useExt ? Xext : g_A;
    int t = threadIdx.x;
    int base = blockIdx.x * 128;

    // Stage W^T hi/lo (2048 b32 each plane)
    {
        const uint32_t* wh = (const uint32_t*)g_Wt_hi[layer];
        const uint32_t* wl = (const uint32_t*)g_Wt_lo[layer];
        #pragma unroll
        for (int it = 0; it < 8; it++) {
            int i = it * 256 + t;              // b32 index 0..2047
            int n = i >> 5, kp = i & 31;
            *(uint32_t*)&wt_hi[n][kp * 2] = wh[i];
            *(uint32_t*)&wt_lo[n][kp * 2] = wl[i];
        }
    }
    // Stage X fp32 -> hi/lo bf16 (128 rows x 64 cols = 2048 float4)
    #pragma unroll
    for (int it = 0; it < 8; it++) {
        int q = it * 256 + t;
        int row = q >> 4;              // 0..127
        int c4 = (q & 15) << 2;        // col 0..60 step 4
        float4 v = make_float4(0.f, 0.f, 0.f, 0.f);
        if (base + row < N) v = *(const float4*)(X + (size_t)(base + row) * 64 + c4);
        __nv_bfloat162 h0 = __floats2bfloat162_rn(v.x, v.y);
        __nv_bfloat162 h1 = __floats2bfloat162_rn(v.z, v.w);
        __nv_bfloat162 l0 = __floats2bfloat162_rn(v.x - __bfloat162float(h0.x),
                                                  v.y - __bfloat162float(h0.y));
        __nv_bfloat162 l1 = __floats2bfloat162_rn(v.z - __bfloat162float(h1.x),
                                                  v.w - __bfloat162float(h1.y));
        *(uint32_t*)&xs_hi[row][c4 + 0] = *(unsigned*)&h0;
        *(uint32_t*)&xs_hi[row][c4 + 2] = *(unsigned*)&h1;
        *(uint32_t*)&xs_lo[row][c4 + 0] = *(unsigned*)&l0;
        *(uint32_t*)&xs_lo[row][c4 + 2] = *(unsigned*)&l1;
    }
    __syncthreads();

    int w = t >> 5;              // warp 0..7 -> rows w*16..+15
    int lane = t & 31;
    int gid = lane >> 2;         // group 0..7
    int tig = lane & 3;          // thread-in-group 0..3

    float d[8][4];
    #pragma unroll
    for (int c = 0; c < 8; c++)
        #pragma unroll
        for (int q = 0; q < 4; q++) d[c][q] = 0.f;

    int ra = w * 16 + gid;
    #pragma unroll
    for (int ks = 0; ks < 4; ks++) {
        int k0 = ks * 16 + tig * 2;
        uint32_t ah0 = *(const uint32_t*)&xs_hi[ra][k0];
        uint32_t ah1 = *(const uint32_t*)&xs_hi[ra + 8][k0];
        uint32_t ah2 = *(const uint32_t*)&xs_hi[ra][k0 + 8];
        uint32_t ah3 = *(const uint32_t*)&xs_hi[ra + 8][k0 + 8];
        uint32_t al0 = *(const uint32_t*)&xs_lo[ra][k0];
        uint32_t al1 = *(const uint32_t*)&xs_lo[ra + 8][k0];
        uint32_t al2 = *(const uint32_t*)&xs_lo[ra][k0 + 8];
        uint32_t al3 = *(const uint32_t*)&xs_lo[ra + 8][k0 + 8];
        #pragma unroll
        for (int c = 0; c < 8; c++) {
            uint32_t bh0 = *(const uint32_t*)&wt_hi[c * 8 + gid][k0];
            uint32_t bh1 = *(const uint32_t*)&wt_hi[c * 8 + gid][k0 + 8];
            uint32_t bl0 = *(const uint32_t*)&wt_lo[c * 8 + gid][k0];
            uint32_t bl1 = *(const uint32_t*)&wt_lo[c * 8 + gid][k0 + 8];
            asm volatile(
                "mma.sync.aligned.m16n8k16.row.col.f32.bf16.bf16.f32 "
                "{%0,%1,%2,%3}, {%4,%5,%6,%7}, {%8,%9}, {%0,%1,%2,%3};"
                : "+f"(d[c][0]), "+f"(d[c][1]), "+f"(d[c][2]), "+f"(d[c][3])
                : "r"(ah0), "r"(ah1), "r"(ah2), "r"(ah3), "r"(bh0), "r"(bh1));
            asm volatile(
                "mma.sync.aligned.m16n8k16.row.col.f32.bf16.bf16.f32 "
                "{%0,%1,%2,%3}, {%4,%5,%6,%7}, {%8,%9}, {%0,%1,%2,%3};"
                : "+f"(d[c][0]), "+f"(d[c][1]), "+f"(d[c][2]), "+f"(d[c][3])
                : "r"(ah0), "r"(ah1), "r"(ah2), "r"(ah3), "r"(bl0), "r"(bl1));
            asm volatile(
                "mma.sync.aligned.m16n8k16.row.col.f32.bf16.bf16.f32 "
                "{%0,%1,%2,%3}, {%4,%5,%6,%7}, {%8,%9}, {%0,%1,%2,%3};"
                : "+f"(d[c][0]), "+f"(d[c][1]), "+f"(d[c][2]), "+f"(d[c][3])
                : "r"(al0), "r"(al1), "r"(al2), "r"(al3), "r"(bh0), "r"(bh1));
        }
    }

    // Epilogue: thread owns rows (base+ra, +8), cols c*8 + tig*2 (+1)
    int row0 = base + ra;
    int row1 = row0 + 8;
    if (row0 < N) {
        float dv = g_dinv[row0];
        #pragma unroll
        for (int c = 0; c < 8; c++) {
            __half2 h = __floats2half2_rn(d[c][0] * dv, d[c][1] * dv);
            *(unsigned*)&g_Bh[(size_t)row0 * 32 + c * 4 + tig] = *(unsigned*)&h;
        }
    }
    if (row1 < N) {
        float dv = g_dinv[row1];
        #pragma unroll
        for (int c = 0; c < 8; c++) {
            __half2 h = __floats2half2_rn(d[c][2] * dv, d[c][3] * dv);
            *(unsigned*)&g_Bh[(size_t)row1 * 32 + c * 4 + tig] = *(unsigned*)&h;
        }
    }
}

// ---------------- aggregation: A[i] = dinv[i]*(B[i] + sum B[src]) + b ----------------
__device__ __forceinline__ void acc_h2(float2& a, __half2 h) {
    float2 f = __half22float2(h);
    a.x += f.x; a.y += f.y;
}

__global__ void __launch_bounds__(256) k_agg(const float* __restrict__ bias,
                                             int relu, int N) {
    int warp = (blockIdx.x * blockDim.x + threadIdx.x) >> 5;
    int lane = threadIdx.x & 31;
    int grp  = lane >> 3;          // 0..3
    int sub  = lane & 7;           // 0..7
    int node = warp * 4 + grp;
    bool active = node < N;
    int nsafe = active ? node : 0;

    const uint4* __restrict__ B4 = (const uint4*)g_Bh;   // B4[node*8 + sub]
    float2 acc[4] = {{0.f,0.f},{0.f,0.f},{0.f,0.f},{0.f,0.f}};

    {   // self loop
        uint4 sv = B4[(size_t)nsafe * 8 + sub];
        acc_h2(acc[0], *(__half2*)&sv.x);
        acc_h2(acc[1], *(__half2*)&sv.y);
        acc_h2(acc[2], *(__half2*)&sv.z);
        acc_h2(acc[3], *(__half2*)&sv.w);
    }

    int beg = active ? g_off[nsafe] : 0;
    int end = active ? g_off[nsafe + 1] : 0;
    int j = beg;
    for (; j + 4 <= end; j += 4) {
        int s0 = g_srcs[j], s1 = g_srcs[j + 1], s2 = g_srcs[j + 2], s3 = g_srcs[j + 3];
        uint4 a = B4[(size_t)s0 * 8 + sub];
        uint4 b = B4[(size_t)s1 * 8 + sub];
        uint4 cc = B4[(size_t)s2 * 8 + sub];
        uint4 d = B4[(size_t)s3 * 8 + sub];
        __half2 t0 = __hadd2(__hadd2(*(__half2*)&a.x, *(__half2*)&b.x),
                             __hadd2(*(__half2*)&cc.x, *(__half2*)&d.x));
        __half2 t1 = __hadd2(__hadd2(*(__half2*)&a.y, *(__half2*)&b.y),
                             __hadd2(*(__half2*)&cc.y, *(__half2*)&d.y));
        __half2 t2 = __hadd2(__hadd2(*(__half2*)&a.z, *(__half2*)&b.z),
                             __hadd2(*(__half2*)&cc.z, *(__half2*)&d.z));
        __half2 t3 = __hadd2(__hadd2(*(__half2*)&a.w, *(__half2*)&b.w),
                             __hadd2(*(__half2*)&cc.w, *(__half2*)&d.w));
        acc_h2(acc[0], t0); acc_h2(acc[1], t1);
        acc_h2(acc[2], t2); acc_h2(acc[3], t3);
    }
    if (j + 2 <= end) {
        int s0 = g_srcs[j], s1 = g_srcs[j + 1];
        uint4 a = B4[(size_t)s0 * 8 + sub];
        uint4 b = B4[(size_t)s1 * 8 + sub];
        acc_h2(acc[0], __hadd2(*(__half2*)&a.x, *(__half2*)&b.x));
        acc_h2(acc[1], __hadd2(*(__half2*)&a.y, *(__half2*)&b.y));
        acc_h2(acc[2], __hadd2(*(__half2*)&a.z, *(__half2*)&b.z));
        acc_h2(acc[3], __hadd2(*(__half2*)&a.w, *(__half2*)&b.w));
        j += 2;
    }
    if (j < end) {
        uint4 a = B4[(size_t)g_srcs[j] * 8 + sub];
        acc_h2(acc[0], *(__half2*)&a.x);
        acc_h2(acc[1], *(__half2*)&a.y);
        acc_h2(acc[2], *(__half2*)&a.z);
        acc_h2(acc[3], *(__half2*)&a.w);
    }

    if (active) {
        float dv = g_dinv[node];
        const float4* bp = (const float4*)(bias + sub * 8);
        float4 b0 = bp[0], b1 = bp[1];
        float4 o0 = make_float4(fmaf(acc[0].x, dv, b0.x), fmaf(acc[0].y, dv, b0.y),
                                fmaf(acc[1].x, dv, b0.z), fmaf(acc[1].y, dv, b0.w));
        float4 o1 = make_float4(fmaf(acc[2].x, dv, b1.x), fmaf(acc[2].y, dv, b1.y),
                                fmaf(acc[3].x, dv, b1.z), fmaf(acc[3].y, dv, b1.w));
        if (relu) {
            o0.x = fmaxf(o0.x, 0.f); o0.y = fmaxf(o0.y, 0.f);
            o0.z = fmaxf(o0.z, 0.f); o0.w = fmaxf(o0.w, 0.f);
            o1.x = fmaxf(o1.x, 0.f); o1.y = fmaxf(o1.y, 0.f);
            o1.z = fmaxf(o1.z, 0.f); o1.w = fmaxf(o1.w, 0.f);
        }
        float4* outp = (float4*)(g_A + (size_t)node * 64 + sub * 8);
        outp[0] = o0; outp[1] = o1;
    }
}

// ---------------- mean pool (batch sorted) ----------------
__global__ void __launch_bounds__(256) k_pool(const int* __restrict__ batch, int N) {
    int warp = (blockIdx.x * blockDim.x + threadIdx.x) >> 5;
    int lane = threadIdx.x & 31;
    int n0 = warp * 32;
    if (n0 >= N) return;
    int nend = min(n0 + 32, N);
    const float2* __restrict__ A2 = (const float2*)g_A;
    float2 acc = make_float2(0.f, 0.f);
    int cur = batch[n0];
    int cnt = 0;
    for (int n = n0; n < nend; n++) {
        int g = batch[n];
        if (g != cur) {
            atomicAdd(&g_sums[cur * 64 + 2 * lane], acc.x);
            atomicAdd(&g_sums[cur * 64 + 2 * lane + 1], acc.y);
            if (lane == 0) atomicAdd(&g_gcnt[cur], cnt);
            acc = make_float2(0.f, 0.f); cnt = 0; cur = g;
        }
        float2 v = A2[(size_t)n * 32 + lane];
        acc.x += v.x; acc.y += v.y; cnt++;
    }
    atomicAdd(&g_sums[cur * 64 + 2 * lane], acc.x);
    atomicAdd(&g_sums[cur * 64 + 2 * lane + 1], acc.y);
    if (lane == 0) atomicAdd(&g_gcnt[cur], cnt);
}

__global__ void k_final(const float* __restrict__ Wlin,
                        const float* __restrict__ blin,
                        float* __restrict__ out) {
    int t = threadIdx.x;
    if (t >= NGRAPH * 2) return;
    int g = t >> 1, o = t & 1;
    float cnt = fmaxf((float)g_gcnt[g], 1.f);
    float s = 0.f;
    #pragma unroll
    for (int f = 0; f < 64; f++) s += g_sums[g * 64 + f] * Wlin[f * 2 + o];
    out[g * 2 + o] = s / cnt + blin[o];
}

// ---------------- launch ----------------
extern "C" void kernel_launch(void* const* d_in, const int* in_sizes, int n_in,
                              void* d_out, int out_size) {
    const float* x     = (const float*)d_in[0];
    const int*   ei    = (const int*)d_in[1];
    const int*   batch = (const int*)d_in[2];
    const float* W1 = (const float*)d_in[3];
    const float* b1 = (const float*)d_in[4];
    const float* W2 = (const float*)d_in[5];
    const float* b2 = (const float*)d_in[6];
    const float* W3 = (const float*)d_in[7];
    const float* b3 = (const float*)d_in[8];
    const float* Wl = (const float*)d_in[9];
    const float* bl = (const float*)d_in[10];
    float* out = (float*)d_out;

    int N = in_sizes[0] / NFEAT;   // 100000
    int E = in_sizes[1] / 2;       // 1000000
    int nb = (N + 1023) / 1024;

    int gemmBlocks = (N + 127) / 128;   // 782
    int aggBlocks  = (N + 31) / 32;     // 8 warps x 4 nodes per block

    // Enable >48KB dynamic smem for the GEMM (host attr call; not a stream op)
    static int smemSet = 0;
    if (!smemSet) {
        cudaFuncSetAttribute(k_gemm_mma, cudaFuncAttributeMaxDynamicSharedMemorySize,
                             GEMM_SMEM);
        smemSet = 1;
    }

    // CSR build; gemm1 at launch slot 4 (profiler captures launch #4)
    k_zero<<<(N + 255) / 256, 256>>>(N);
    k_hist<<<(E + 255) / 256, 256>>>(ei, E);
    k_dinv<<<(N + 255) / 256, 256>>>(N, W1, W2, W3);
    k_gemm_mma<<<gemmBlocks, 256, GEMM_SMEM>>>(x, N, 1, 0);    // launch #4
    k_scan1<<<nb, 1024>>>(N);
    k_scan2<<<1, 128>>>(nb, N);
    k_scan3<<<nb, 1024>>>(N);
    k_place<<<(E + 255) / 256, 256>>>(ei, E);

    k_agg<<<aggBlocks, 256>>>(b1, 1, N);
    k_gemm_mma<<<gemmBlocks, 256, GEMM_SMEM>>>(nullptr, N, 0, 1);
    k_agg<<<aggBlocks, 256>>>(b2, 1, N);
    k_gemm_mma<<<gemmBlocks, 256, GEMM_SMEM>>>(nullptr, N, 0, 2);
    k_agg<<<aggBlocks, 256>>>(b3, 0, N);

    int poolWarps = (N + 31) / 32;
    k_pool<<<(poolWarps + 7) / 8, 256>>>(batch, N);
    k_final<<<1, 128>>>(Wl, bl, out);
}